// round 7
// baseline (speedup 1.0000x reference)
#include <cuda_runtime.h>

// Circuit_87634512707722 — batched 3-qubit statevector:
//   H(q0), H(q1), RX(theta0)(q0), RX(theta1)(q1), CNOT(ctrl=q0, tgt=q2)
// Fused per qubit: U_q = RX(theta_q)·H, a = cos(th/2)/√2, b = sin(th/2)/√2.
//
// R7: single-wave persistent kernel. 512 CTAs x 256 thr (< 592 = 148 SMs x 4
// CTAs resident) -> zero wave transitions. Each thread does 16 states,
// fully unrolled stride loop with next-iteration LDG.256 prefetch issued
// before current-iteration compute: DRAM pipeline continuously fed.
// Dense 256-bit ld/st (R6 layout); default cache policy everywhere
// (evict hints proven no-op/harmful in R3-R6).

#define BQ      2097152
#define NBLOCKS 512
#define NTH     256
#define STRIDE  (NBLOCKS * NTH)          // 131072 threads
#define ITERS   (BQ / STRIDE)            // 16, exact

__device__ __forceinline__ void ld256(const float* p, float* v) {
    asm volatile("ld.global.nc.v8.b32 {%0,%1,%2,%3,%4,%5,%6,%7}, [%8];"
                 : "=f"(v[0]), "=f"(v[1]), "=f"(v[2]), "=f"(v[3]),
                   "=f"(v[4]), "=f"(v[5]), "=f"(v[6]), "=f"(v[7])
                 : "l"(p));
}

__device__ __forceinline__ void st256(float* p, const float* v) {
    asm volatile("st.global.v8.b32 [%0], {%1,%2,%3,%4,%5,%6,%7,%8};"
                 :: "l"(p),
                    "f"(v[0]), "f"(v[1]), "f"(v[2]), "f"(v[3]),
                    "f"(v[4]), "f"(v[5]), "f"(v[6]), "f"(v[7])
                 : "memory");
}

__device__ __forceinline__ void pair_op(float a, float b,
                                        float& x0r, float& x0i,
                                        float& x1r, float& x1i) {
    // p = (a - i b) * x0 ; q = (a + i b) * x1 ; y0 = p+q ; y1 = p-q
    float pr = fmaf(a, x0r,  b * x0i);
    float pi = fmaf(a, x0i, -b * x0r);
    float qr = fmaf(a, x1r, -b * x1i);
    float qi = fmaf(a, x1i,  b * x1r);
    x0r = pr + qr;  x0i = pi + qi;
    x1r = pr - qr;  x1i = pi - qi;
}

__device__ __forceinline__ void apply_gates(float a0, float b0, float a1, float b1,
                                            float* re, float* im) {
    // Qubit 0 (amp bit 2): pairs (k, k+4)
#pragma unroll
    for (int k = 0; k < 4; k++)
        pair_op(a0, b0, re[k], im[k], re[k + 4], im[k + 4]);
    // Qubit 1 (amp bit 1): pairs (k, k+2), k in {0,1,4,5}
#pragma unroll
    for (int k = 0; k < 2; k++) {
        pair_op(a1, b1, re[k],     im[k],     re[k + 2], im[k + 2]);
        pair_op(a1, b1, re[k + 4], im[k + 4], re[k + 6], im[k + 6]);
    }
}

__global__ __launch_bounds__(NTH)
void circuit_kernel(const float* __restrict__ xr,
                    const float* __restrict__ xi,
                    const float* __restrict__ theta,
                    float* __restrict__ out) {
    int t = blockIdx.x * NTH + threadIdx.x;

    // Gate constants (uniform)
    float t0 = theta[0] * 0.5f;
    float t1 = theta[1] * 0.5f;
    const float is2 = 0.70710678118654752f;
    float s0, c0, s1, c1;
    __sincosf(t0, &s0, &c0);
    __sincosf(t1, &s1, &c1);
    float a0 = c0 * is2, b0 = s0 * is2;
    float a1 = c1 * is2, b1 = s1 * is2;

    float reA[8], imA[8], reB[8], imB[8];

    // Prologue: prefetch iteration 0
    ld256(xr + 8 * t, reA);
    ld256(xi + 8 * t, imA);

    int b = t;
#pragma unroll
    for (int it = 0; it < ITERS; ++it) {
        int bn = b + STRIDE;
        // Prefetch next iteration before touching current data
        if (it + 1 < ITERS) {
            ld256(xr + 8 * bn, reB);
            ld256(xi + 8 * bn, imB);
        }

        apply_gates(a0, b0, a1, b1, reA, imA);

        // CNOT(ctrl=q0, tgt=q2): swap amps 4<->5, 6<->7, folded into the
        // interleaved (8,2) re/im store. 2 x 256-bit stores, 64 B contiguous.
        float o0[8] = {reA[0], imA[0], reA[1], imA[1],
                       reA[2], imA[2], reA[3], imA[3]};
        float o1[8] = {reA[5], imA[5], reA[4], imA[4],
                       reA[7], imA[7], reA[6], imA[6]};
        st256(out + 16 * b,     o0);
        st256(out + 16 * b + 8, o1);

        // Rotate buffers (full unroll -> register renaming, no real moves)
#pragma unroll
        for (int k = 0; k < 8; k++) { reA[k] = reB[k]; imA[k] = imB[k]; }
        b = bn;
    }
}

extern "C" void kernel_launch(void* const* d_in, const int* in_sizes, int n_in,
                              void* d_out, int out_size) {
    const float* xr = (const float*)d_in[0];
    const float* xi = (const float*)d_in[1];
    const float* th = (const float*)d_in[2];
    // d_in[3] = angle, dead argument

    float* out = (float*)d_out;

    circuit_kernel<<<NBLOCKS, NTH>>>(xr, xi, th, out);
}

// round 8
// speedup vs baseline: 1.1301x; 1.1301x over previous
#include <cuda_runtime.h>

// Circuit_87634512707722 — batched 3-qubit statevector:
//   H(q0), H(q1), RX(theta0)(q0), RX(theta1)(q1), CNOT(ctrl=q0, tgt=q2)
// Fused per qubit: U_q = RX(theta_q)·H = [[a-ib, a+ib],[a-ib, -(a+ib)]],
//   a = cos(theta/2)/√2, b = sin(theta/2)/√2.
//
// FINAL (R2 config — best measured: kernel 35.6us, DRAM 75.5%, eff. app
// bandwidth 7.5 TB/s = 94% of spec; cache hints / persistence / MLP
// restructuring all measured neutral or negative in R3-R7).
//
// Quarter-state lane mapping for perfect coalescing:
//   warp w covers 16 states. lane l owns amps {2(l&3), 2(l&3)+1} of
//   state (16w + (l>>2)) and state (16w + 8 + (l>>2)).
//   amp bit2 (q0) == lane bit1  -> exchange via shfl_xor(2)
//   amp bit1 (q1) == lane bit0  -> exchange via shfl_xor(1)
//   amp bit0 (q2) in-thread     -> CNOT = local swap when q0 half is 1
// All loads:  LDG.64  xr2[64w+l], xr2[64w+32+l] (contiguous 256B/warp)
// All stores: STG.128 out4[64w+l], out4[64w+32+l] (contiguous 512B/warp)

#define BQ 2097152
#define NTHREADS (2 * BQ)   // 2 threads per state (quarter-state each, 2 states/thread)

__device__ __forceinline__ void gate_round(float a, float bs, float sz, int xorm,
                                           float& x0r, float& x0i,
                                           float& x1r, float& x1i) {
    // z = (a - i*bs) * x  (bs carries the per-half sign; sz = combine sign)
    float z0r = fmaf(a, x0r,  bs * x0i);
    float z0i = fmaf(a, x0i, -bs * x0r);
    float z1r = fmaf(a, x1r,  bs * x1i);
    float z1i = fmaf(a, x1i, -bs * x1r);
    float w0r = __shfl_xor_sync(0xffffffffu, z0r, xorm);
    float w0i = __shfl_xor_sync(0xffffffffu, z0i, xorm);
    float w1r = __shfl_xor_sync(0xffffffffu, z1r, xorm);
    float w1i = __shfl_xor_sync(0xffffffffu, z1i, xorm);
    // half0: y = z + w ; half1: y = w - z
    x0r = fmaf(sz, z0r, w0r);
    x0i = fmaf(sz, z0i, w0i);
    x1r = fmaf(sz, z1r, w1r);
    x1i = fmaf(sz, z1i, w1i);
}

__global__ __launch_bounds__(256)
void circuit_kernel(const float2* __restrict__ xr2,
                    const float2* __restrict__ xi2,
                    const float* __restrict__ theta,
                    float4* __restrict__ out4) {
    int t = blockIdx.x * blockDim.x + threadIdx.x;
    int l = t & 31;
    int base = ((t >> 5) << 6) + l;   // float2-index for loads AND float4-index for stores

    // Front-batch all 4 coalesced loads (MLP=4)
    float2 ra  = xr2[base];
    float2 rb  = xr2[base + 32];
    float2 ia  = xi2[base];
    float2 ib_ = xi2[base + 32];

    // Gate constants (uniform; MUFU hidden under LDG latency)
    float t0 = theta[0] * 0.5f;
    float t1 = theta[1] * 0.5f;
    const float is2 = 0.70710678118654752f;
    float s0, c0, s1, c1;
    __sincosf(t0, &s0, &c0);
    __sincosf(t1, &s1, &c1);
    float a0 = c0 * is2, b0 = s0 * is2;
    float a1 = c1 * is2, b1 = s1 * is2;

    int h0 = (l >> 1) & 1;   // this lane's q0 bit value
    int h1 = l & 1;          // this lane's q1 bit value
    float bs0 = h0 ? -b0 : b0;
    float sz0 = h0 ? -1.0f : 1.0f;
    float bs1 = h1 ? -b1 : b1;
    float sz1 = h1 ? -1.0f : 1.0f;

    // State A amps: x0=(ra.x, ia.x), x1=(ra.y, ia.y); state B likewise.
    // Qubit 0 gate (partner lane l^2)
    gate_round(a0, bs0, sz0, 2, ra.x, ia.x,  ra.y, ia.y);
    gate_round(a0, bs0, sz0, 2, rb.x, ib_.x, rb.y, ib_.y);
    // Qubit 1 gate (partner lane l^1)
    gate_round(a1, bs1, sz1, 1, ra.x, ia.x,  ra.y, ia.y);
    gate_round(a1, bs1, sz1, 1, rb.x, ib_.x, rb.y, ib_.y);

    // CNOT(ctrl=q0, tgt=q2): lanes with q0==1 swap their local amp pair (bit0 flip)
    float A0r = h0 ? ra.y  : ra.x;
    float A0i = h0 ? ia.y  : ia.x;
    float A1r = h0 ? ra.x  : ra.y;
    float A1i = h0 ? ia.x  : ia.y;
    float B0r = h0 ? rb.y  : rb.x;
    float B0i = h0 ? ib_.y : ib_.x;
    float B1r = h0 ? rb.x  : rb.y;
    float B1i = h0 ? ib_.x : ib_.y;

    // Interleaved (re,im) output chunks, fully coalesced stores
    out4[base]      = make_float4(A0r, A0i, A1r, A1i);
    out4[base + 32] = make_float4(B0r, B0i, B1r, B1i);
}

extern "C" void kernel_launch(void* const* d_in, const int* in_sizes, int n_in,
                              void* d_out, int out_size) {
    const float2* xr = (const float2*)d_in[0];
    const float2* xi = (const float2*)d_in[1];
    const float*  th = (const float*)d_in[2];
    // d_in[3] = angle, dead argument

    float4* out = (float4*)d_out;

    const int threads = 256;
    const int blocks = NTHREADS / threads;   // 16384, exact
    circuit_kernel<<<blocks, threads>>>(xr, xi, th, out);
}